// round 12
// baseline (speedup 1.0000x reference)
#include <cuda_runtime.h>
#include <cstddef>

#define N_NODES 25000
#define N_EDGES 200000
#define NC 32

#define CAP 64                   // max in-edges per node bucket (Poisson(8): P(>=64) ~ 1e-35)
#define REC_STRIDE 16            // floats per packed edge record (4 x float4)
#define MIX_THREADS 416          // 13 warps
#define MIX_NB 16                // nodes per mix block
#define MIX_BLOCKS 1563          // 1563*16 >= 25000
#define HS_STRIDE 36             // padded component stride (36 floats, 16B-aligned)

// ---------------- scratch (static device globals: allocation-free) ----------------
__device__ float g_hm[(size_t)N_NODES * 13 * NC];            // mixed features [n][comp][c]
__device__ int   g_count[N_NODES];                           // cursor/degree; zeroed by node_kernel
__device__ float g_rec[(size_t)N_NODES * CAP * REC_STRIDE];  // bucketed per-edge records

// ---------------- K1: channel mix ----------------
__global__ void __launch_bounds__(MIX_THREADS) mix_kernel(
    const float* __restrict__ h0, const float* __restrict__ h1,
    const float* __restrict__ h2, const float* __restrict__ W)
{
    __shared__ float w_s[3 * 32 * 33];                  // weights, padded rows
    __shared__ float h_s[MIX_NB * 13 * HS_STRIDE];      // staged node features [b][comp][c]

    int tid = threadIdx.x;
    int w = tid >> 5;          // component 0..12
    int lane = tid & 31;       // output channel
    int r = (w == 0) ? 0 : (w < 4 ? 1 : 2);

    for (int idx = tid; idx < 3 * 32 * 32; idx += MIX_THREADS) {
        int rr = idx >> 10, rem = idx & 1023, c = rem >> 5, j = rem & 31;
        w_s[(rr * 32 + c) * 33 + j] = W[idx];
    }

    // coalesced staging: thread t copies float t of each node's 416-float block
    int nb = blockIdx.x * MIX_NB;
    int t = tid;               // 0..415, contiguous within each source segment
    int comp, c;
    const float* src0;
    if (t < 32)       { comp = 0;            c = t;             src0 = h0 + t;  }
    else if (t < 128) { int t1 = t - 32;     comp = 1 + t1 % 3; c = t1 / 3;     src0 = h1 + t1; }
    else              { int t2 = t - 128;    comp = 4 + t2 % 9; c = t2 / 9;     src0 = h2 + t2; }
    int sseg = (t < 32) ? 32 : (t < 128 ? 96 : 288);   // per-node stride of my segment
    float* dst = h_s + comp * HS_STRIDE + c;
#pragma unroll
    for (int b = 0; b < MIX_NB; b++) {
        int n = nb + b;
        float v = 0.f;
        if (n < N_NODES) v = src0[(size_t)n * sseg];   // fully coalesced
        dst[b * 13 * HS_STRIDE] = v;
    }
    __syncthreads();

    float wreg[32];
    {
        const float* base = w_s + (r * 32 + lane) * 33;
#pragma unroll
        for (int j = 0; j < 32; j++) wreg[j] = base[j];
    }

#pragma unroll 1
    for (int b = 0; b < MIX_NB; b++) {
        int n = nb + b;
        if (n >= N_NODES) break;
        const float4* hp = (const float4*)(h_s + (b * 13 + w) * HS_STRIDE);
        float a0 = 0.f, a1 = 0.f, a2 = 0.f, a3 = 0.f;
#pragma unroll
        for (int jj = 0; jj < 8; jj++) {
            float4 q = hp[jj];                 // broadcast LDS.128
            a0 = fmaf(q.x, wreg[jj * 4 + 0], a0);
            a1 = fmaf(q.y, wreg[jj * 4 + 1], a1);
            a2 = fmaf(q.z, wreg[jj * 4 + 2], a2);
            a3 = fmaf(q.w, wreg[jj * 4 + 3], a3);
        }
        g_hm[((size_t)n * 13 + w) * 32 + lane] = (a0 + a1) + (a2 + a3);
    }
}

// ---------------- K2: scatter packed edge records into node buckets ----------------
// Runs RIGHT BEFORE node_kernel so g_rec lines are L2-resident when consumed.
__global__ void scatter_kernel(
    const int* __restrict__ eidx, const float* __restrict__ ea0,
    const float* __restrict__ ea1, const float* __restrict__ ea2)
{
    int e = blockIdx.x * blockDim.x + threadIdx.x;
    if (e >= N_EDGES) return;
    int send = eidx[e];
    int recv = eidx[N_EDGES + e];
    float a0 = ea0[e];
    float a1x = ea1[e * 3 + 0], a1y = ea1[e * 3 + 1], a1z = ea1[e * 3 + 2];
    float A2[9];
#pragma unroll
    for (int k = 0; k < 9; k++) A2[k] = ea2[e * 9 + k];
    float u = a0 + A2[0] + A2[4] + A2[8];

    int slot = atomicAdd(&g_count[send], 1);
    float4* r = (float4*)(g_rec + ((size_t)send * CAP + slot) * REC_STRIDE);
    r[0] = make_float4(u, a1x, a1y, a1z);
    r[1] = make_float4(A2[0], A2[1], A2[2], A2[3]);
    r[2] = make_float4(A2[4], A2[5], A2[6], A2[7]);
    r[3] = make_float4(A2[8], __int_as_float(recv), 0.f, 0.f);
}

// ---------------- per-edge compute (round-7 known-good 64us loop body) ----------------
struct EdgeIn {
    float H0, H1[3], H2[9];
    float u, a1[3], A2[9];
};

__device__ __forceinline__ void load_edge(const float* __restrict__ recp, int lane, EdgeIn& d) {
    const float4* rec = (const float4*)recp;
    float4 ra = rec[0], rb = rec[1], rc4 = rec[2], rd = rec[3];   // broadcast loads
    d.u = ra.x; d.a1[0] = ra.y; d.a1[1] = ra.z; d.a1[2] = ra.w;
    d.A2[0] = rb.x; d.A2[1] = rb.y; d.A2[2] = rb.z; d.A2[3] = rb.w;
    d.A2[4] = rc4.x; d.A2[5] = rc4.y; d.A2[6] = rc4.z; d.A2[7] = rc4.w;
    d.A2[8] = rd.x;
    int recv = __float_as_int(rd.y);
    const float* hm = g_hm + (size_t)recv * (13 * 32) + lane;
    d.H0 = hm[0];
#pragma unroll
    for (int k = 0; k < 3; k++) d.H1[k] = hm[(1 + k) * 32];
#pragma unroll
    for (int k = 0; k < 9; k++) d.H2[k] = hm[(4 + k) * 32];
}

__device__ __forceinline__ void compute_edge(const EdgeIn& d, float acc[13]) {
    float tH = d.H2[0] + d.H2[4] + d.H2[8];
    float u = d.u;
    float P = d.H0 + tH;

    float S[9], G[9];
#pragma unroll
    for (int i = 0; i < 3; i++)
#pragma unroll
        for (int j = 0; j < 3; j++) {
            S[i * 3 + j] = d.A2[i * 3 + j] + d.A2[j * 3 + i];
            G[i * 3 + j] = d.H2[i * 3 + j] + d.H2[j * 3 + i];
        }

    float r0 = P * u;
#pragma unroll
    for (int k = 0; k < 3; k++) r0 = fmaf(d.H1[k], d.a1[k], r0);
#pragma unroll
    for (int k = 0; k < 9; k++) r0 = fmaf(d.H2[k], S[k], r0);
    acc[0] += r0;

#pragma unroll
    for (int x = 0; x < 3; x++) {
        float r1 = fmaf(P, d.a1[x], u * d.H1[x]);
#pragma unroll
        for (int k = 0; k < 3; k++) r1 = fmaf(S[x * 3 + k], d.H1[k], r1);
#pragma unroll
        for (int k = 0; k < 3; k++) r1 = fmaf(G[x * 3 + k], d.a1[k], r1);
        acc[1 + x] += r1;
    }

#pragma unroll
    for (int i = 0; i < 3; i++)
#pragma unroll
        for (int j = 0; j < 3; j++) {
            float r2 = fmaf(P, d.A2[i * 3 + j], fmaf(u, d.H2[i * 3 + j], d.H1[i] * d.a1[j]));
#pragma unroll
            for (int k = 0; k < 3; k++) r2 = fmaf(G[i * 3 + k], S[j * 3 + k], r2);
            acc[4 + i * 3 + j] += r2;
        }
}

// ---------------- K3: warp per node over its bucket; resets cursor for next replay ----------------
__global__ void __launch_bounds__(256) node_kernel(float* __restrict__ out) {
    int gw = (blockIdx.x * blockDim.x + threadIdx.x) >> 5;
    int lane = threadIdx.x & 31;
    if (gw >= N_NODES) return;
    int n = gw;

    int deg = g_count[n];                    // broadcast load (all lanes same addr)
    if (lane == 0) g_count[n] = 0;           // reset cursor for next graph replay

    const float* base = g_rec + (size_t)n * CAP * REC_STRIDE;

    float acc[13];
#pragma unroll
    for (int k = 0; k < 13; k++) acc[k] = 0.f;

    int p = 0;
    for (; p + 1 < deg; p += 2) {
        EdgeIn dA, dB;
        load_edge(base + (size_t)p * REC_STRIDE, lane, dA);        // both edges' loads
        load_edge(base + (size_t)(p + 1) * REC_STRIDE, lane, dB);  // issued before compute
        compute_edge(dA, acc);
        compute_edge(dB, acc);
    }
    if (p < deg) {
        EdgeIn dA;
        load_edge(base + (size_t)p * REC_STRIDE, lane, dA);
        compute_edge(dA, acc);
    }

    float* out0 = out;
    float* out1 = out + (size_t)N_NODES * NC;
    float* out2 = out + (size_t)N_NODES * NC * 4;
    out0[n * 32 + lane] = acc[0];
#pragma unroll
    for (int x = 0; x < 3; x++) out1[(n * 32 + lane) * 3 + x] = acc[1 + x];
#pragma unroll
    for (int k = 0; k < 9; k++) out2[(n * 32 + lane) * 9 + k] = acc[4 + k];
}

// ---------------- launch: mix -> scatter -> node (records hot in L2 for node) ----------------
extern "C" void kernel_launch(void* const* d_in, const int* in_sizes, int n_in,
                              void* d_out, int out_size) {
    const float* h0  = (const float*)d_in[0];
    const float* h1  = (const float*)d_in[1];
    const float* h2  = (const float*)d_in[2];
    // d_in[3] = rel_pos (unused by the math)
    const float* ea0 = (const float*)d_in[4];
    const float* ea1 = (const float*)d_in[5];
    const float* ea2 = (const float*)d_in[6];
    const float* W   = (const float*)d_in[7];
    const int*  eidx = (const int*)d_in[8];
    float* out = (float*)d_out;

    mix_kernel<<<MIX_BLOCKS, MIX_THREADS>>>(h0, h1, h2, W);
    scatter_kernel<<<(N_EDGES + 255) / 256, 256>>>(eidx, ea0, ea1, ea2);
    node_kernel<<<(N_NODES * 32 + 255) / 256, 256>>>(out);
}

// round 13
// speedup vs baseline: 1.1808x; 1.1808x over previous
#include <cuda_runtime.h>
#include <cstddef>

#define N_NODES 25000
#define N_EDGES 200000
#define NC 32

#define FUSED_THREADS 416        // 13 warps
#define HIST_BLOCKS 481          // 481*416 >= 200000
#define MIX_NB 16                // nodes per mix block
#define MIX_BLOCKS 1563          // 1563*16 >= 25000
#define REC_STRIDE 16            // floats per packed edge record (4 x float4)
#define HS_STRIDE 36             // padded component stride (36 floats = 144B, 16B-aligned)
#define WS_STRIDE 34             // weight row stride (34 floats: 8B-aligned rows, conflict-free LDS.64)

typedef unsigned long long u64;

// ---------------- scratch (static device globals: allocation-free) ----------------
__device__ float g_hm[(size_t)N_NODES * 13 * NC];       // mixed features [n][comp(13)][c(32)]
__device__ int   g_count[N_NODES];                      // zero at load; re-zeroed by node_kernel
__device__ int   g_off[N_NODES + 1];
__device__ int   g_cursor[N_NODES];
__device__ float g_rec[(size_t)N_EDGES * REC_STRIDE];   // packed per-edge record in CSR order

// ---------------- packed f32x2 helpers (sm_100+) ----------------
__device__ __forceinline__ u64 fma2(u64 a, u64 b, u64 c) {
    u64 d; asm("fma.rn.f32x2 %0, %1, %2, %3;" : "=l"(d) : "l"(a), "l"(b), "l"(c)); return d;
}
__device__ __forceinline__ u64 add2(u64 a, u64 b) {
    u64 d; asm("add.rn.f32x2 %0, %1, %2;" : "=l"(d) : "l"(a), "l"(b)); return d;
}
__device__ __forceinline__ float upk_sum(u64 v) {
    float a, b; asm("mov.b64 {%0, %1}, %2;" : "=f"(a), "=f"(b) : "l"(v)); return a + b;
}

// ---------------- K1: fused histogram (blocks 0..480) + channel mix (rest) ----------------
__global__ void __launch_bounds__(FUSED_THREADS) hist_mix_kernel(
    const int* __restrict__ eidx,
    const float* __restrict__ h0, const float* __restrict__ h1,
    const float* __restrict__ h2, const float* __restrict__ W)
{
    if (blockIdx.x < HIST_BLOCKS) {
        int e = blockIdx.x * FUSED_THREADS + threadIdx.x;
        if (e < N_EDGES) atomicAdd(&g_count[eidx[e]], 1);   // row 0 = send
        return;
    }

    __shared__ alignas(16) float w_s[3 * 32 * WS_STRIDE];   // weights, padded rows
    __shared__ alignas(16) float h_s[MIX_NB * 13 * HS_STRIDE]; // staged features [b][comp][c]

    int tid = threadIdx.x;
    int w = tid >> 5;          // component 0..12
    int lane = tid & 31;       // output channel
    int r = (w == 0) ? 0 : (w < 4 ? 1 : 2);

    for (int idx = tid; idx < 3 * 32 * 32; idx += FUSED_THREADS) {
        int rr = idx >> 10, rem = idx & 1023, c = rem >> 5, j = rem & 31;
        w_s[(rr * 32 + c) * WS_STRIDE + j] = W[idx];
    }

    // ---- coalesced staging: thread t copies float t of each node's 416-float block ----
    int nb = (blockIdx.x - HIST_BLOCKS) * MIX_NB;
    int t = tid;               // 0..415, contiguous within each source segment
    int comp, c;
    const float* src0;
    if (t < 32)       { comp = 0;            c = t;             src0 = h0 + t;  }
    else if (t < 128) { int t1 = t - 32;     comp = 1 + t1 % 3; c = t1 / 3;     src0 = h1 + t1; }
    else              { int t2 = t - 128;    comp = 4 + t2 % 9; c = t2 / 9;     src0 = h2 + t2; }
    int sseg = (t < 32) ? 32 : (t < 128 ? 96 : 288);   // per-node stride of my segment
    float* dst = h_s + comp * HS_STRIDE + c;
#pragma unroll
    for (int b = 0; b < MIX_NB; b++) {
        int n = nb + b;
        float v = 0.f;
        if (n < N_NODES) v = src0[(size_t)n * sseg];   // fully coalesced
        dst[b * 13 * HS_STRIDE] = v;
    }
    __syncthreads();

    // j-packed weights: wreg2[j] = {w[2j], w[2j+1]} loaded directly as u64 (adjacent floats)
    u64 wreg2[16];
    {
        const u64* base = (const u64*)(w_s + (r * 32 + lane) * WS_STRIDE);
#pragma unroll
        for (int j = 0; j < 16; j++) wreg2[j] = base[j];
    }

#pragma unroll 2
    for (int b = 0; b < MIX_NB; b++) {
        int n = nb + b;
        if (n >= N_NODES) break;
        const ulonglong2* hp = (const ulonglong2*)(h_s + (b * 13 + w) * HS_STRIDE);
        u64 acc0 = 0ull, acc1 = 0ull;     // {even-partial, odd-partial} pairs
#pragma unroll
        for (int jj = 0; jj < 8; jj++) {
            ulonglong2 q = hp[jj];         // broadcast LDS.128 = 2 packed j-pairs
            acc0 = fma2(q.x, wreg2[jj * 2 + 0], acc0);
            acc1 = fma2(q.y, wreg2[jj * 2 + 1], acc1);
        }
        g_hm[((size_t)n * 13 + w) * 32 + lane] = upk_sum(add2(acc0, acc1));
    }
}

// ---------------- K2: one-pass exclusive scan (1024 threads x 25-elem chunks) ----------------
__global__ void scan_kernel() {
    __shared__ int warp_sums[32];
    const int CH = 25;
    int tid = threadIdx.x;
    int lane = tid & 31, wid = tid >> 5;
    int base = tid * CH;

    int local[CH];
    int sum = 0;
#pragma unroll
    for (int k = 0; k < CH; k++) {
        int i = base + k;
        int v = (i < N_NODES) ? g_count[i] : 0;
        local[k] = v; sum += v;
    }
    int x = sum;
#pragma unroll
    for (int ofs = 1; ofs < 32; ofs <<= 1) {
        int t = __shfl_up_sync(0xffffffffu, x, ofs);
        if (lane >= ofs) x += t;
    }
    if (lane == 31) warp_sums[wid] = x;
    __syncthreads();
    if (wid == 0) {
        int wv = warp_sums[lane];
#pragma unroll
        for (int ofs = 1; ofs < 32; ofs <<= 1) {
            int t = __shfl_up_sync(0xffffffffu, wv, ofs);
            if (lane >= ofs) wv += t;
        }
        warp_sums[lane] = wv;
    }
    __syncthreads();
    int warp_excl = (wid == 0) ? 0 : warp_sums[wid - 1];
    int run = warp_excl + x - sum;
#pragma unroll
    for (int k = 0; k < CH; k++) {
        int i = base + k;
        if (i < N_NODES) { g_off[i] = run; g_cursor[i] = run; }
        run += local[k];
    }
    if (tid == 1023) g_off[N_NODES] = run;
}

// ---------------- K3: scatter packed edge records into dense CSR slots ----------------
__global__ void scatter_pack_kernel(
    const int* __restrict__ eidx, const float* __restrict__ ea0,
    const float* __restrict__ ea1, const float* __restrict__ ea2)
{
    int e = blockIdx.x * blockDim.x + threadIdx.x;
    if (e >= N_EDGES) return;
    int send = eidx[e];
    int recv = eidx[N_EDGES + e];
    float a0 = ea0[e];
    float a1x = ea1[e * 3 + 0], a1y = ea1[e * 3 + 1], a1z = ea1[e * 3 + 2];
    float A2[9];
#pragma unroll
    for (int k = 0; k < 9; k++) A2[k] = ea2[e * 9 + k];
    float u = a0 + A2[0] + A2[4] + A2[8];

    int pos = atomicAdd(&g_cursor[send], 1);
    float4* r = (float4*)(g_rec + (size_t)pos * REC_STRIDE);
    r[0] = make_float4(u, a1x, a1y, a1z);
    r[1] = make_float4(A2[0], A2[1], A2[2], A2[3]);
    r[2] = make_float4(A2[4], A2[5], A2[6], A2[7]);
    r[3] = make_float4(A2[8], __int_as_float(recv), 0.f, 0.f);
}

// ---------------- per-edge compute (round-7 known-good 64us loop body) ----------------
struct EdgeIn {
    float H0, H1[3], H2[9];
    float u, a1[3], A2[9];
};

__device__ __forceinline__ void load_edge(int p, int lane, EdgeIn& d) {
    const float4* rec = (const float4*)(g_rec + (size_t)p * REC_STRIDE);
    float4 ra = rec[0], rb = rec[1], rc4 = rec[2], rd = rec[3];   // broadcast loads
    d.u = ra.x; d.a1[0] = ra.y; d.a1[1] = ra.z; d.a1[2] = ra.w;
    d.A2[0] = rb.x; d.A2[1] = rb.y; d.A2[2] = rb.z; d.A2[3] = rb.w;
    d.A2[4] = rc4.x; d.A2[5] = rc4.y; d.A2[6] = rc4.z; d.A2[7] = rc4.w;
    d.A2[8] = rd.x;
    int recv = __float_as_int(rd.y);
    const float* hm = g_hm + (size_t)recv * (13 * 32) + lane;
    d.H0 = hm[0];
#pragma unroll
    for (int k = 0; k < 3; k++) d.H1[k] = hm[(1 + k) * 32];
#pragma unroll
    for (int k = 0; k < 9; k++) d.H2[k] = hm[(4 + k) * 32];
}

__device__ __forceinline__ void compute_edge(const EdgeIn& d, float acc[13]) {
    float tH = d.H2[0] + d.H2[4] + d.H2[8];
    float u = d.u;
    float P = d.H0 + tH;

    float S[9], G[9];
#pragma unroll
    for (int i = 0; i < 3; i++)
#pragma unroll
        for (int j = 0; j < 3; j++) {
            S[i * 3 + j] = d.A2[i * 3 + j] + d.A2[j * 3 + i];
            G[i * 3 + j] = d.H2[i * 3 + j] + d.H2[j * 3 + i];
        }

    float r0 = P * u;
#pragma unroll
    for (int k = 0; k < 3; k++) r0 = fmaf(d.H1[k], d.a1[k], r0);
#pragma unroll
    for (int k = 0; k < 9; k++) r0 = fmaf(d.H2[k], S[k], r0);
    acc[0] += r0;

#pragma unroll
    for (int x = 0; x < 3; x++) {
        float r1 = fmaf(P, d.a1[x], u * d.H1[x]);
#pragma unroll
        for (int k = 0; k < 3; k++) r1 = fmaf(S[x * 3 + k], d.H1[k], r1);
#pragma unroll
        for (int k = 0; k < 3; k++) r1 = fmaf(G[x * 3 + k], d.a1[k], r1);
        acc[1 + x] += r1;
    }

#pragma unroll
    for (int i = 0; i < 3; i++)
#pragma unroll
        for (int j = 0; j < 3; j++) {
            float r2 = fmaf(P, d.A2[i * 3 + j], fmaf(u, d.H2[i * 3 + j], d.H1[i] * d.a1[j]));
#pragma unroll
            for (int k = 0; k < 3; k++) r2 = fmaf(G[i * 3 + k], S[j * 3 + k], r2);
            acc[4 + i * 3 + j] += r2;
        }
}

// ---------------- K4: warp per node; re-zeroes g_count for the next replay ----------------
__global__ void __launch_bounds__(256) node_kernel(float* __restrict__ out) {
    int gid = blockIdx.x * blockDim.x + threadIdx.x;
    if (gid < N_NODES) g_count[gid] = 0;     // prep for next replay (hist is next launch)

    int gw = gid >> 5;
    int lane = threadIdx.x & 31;
    if (gw >= N_NODES) return;
    int n = gw;
    int beg = g_off[n], end = g_off[n + 1];

    float acc[13];
#pragma unroll
    for (int k = 0; k < 13; k++) acc[k] = 0.f;

    int p = beg;
    for (; p + 1 < end; p += 2) {
        EdgeIn dA, dB;
        load_edge(p, lane, dA);       // all loads for both edges issued
        load_edge(p + 1, lane, dB);   // before any compute -> 2x MLP
        compute_edge(dA, acc);
        compute_edge(dB, acc);
    }
    if (p < end) {
        EdgeIn dA;
        load_edge(p, lane, dA);
        compute_edge(dA, acc);
    }

    float* out0 = out;
    float* out1 = out + (size_t)N_NODES * NC;
    float* out2 = out + (size_t)N_NODES * NC * 4;
    out0[n * 32 + lane] = acc[0];
#pragma unroll
    for (int x = 0; x < 3; x++) out1[(n * 32 + lane) * 3 + x] = acc[1 + x];
#pragma unroll
    for (int k = 0; k < 9; k++) out2[(n * 32 + lane) * 9 + k] = acc[4 + k];
}

// ---------------- launch ----------------
extern "C" void kernel_launch(void* const* d_in, const int* in_sizes, int n_in,
                              void* d_out, int out_size) {
    const float* h0  = (const float*)d_in[0];
    const float* h1  = (const float*)d_in[1];
    const float* h2  = (const float*)d_in[2];
    // d_in[3] = rel_pos (unused by the math)
    const float* ea0 = (const float*)d_in[4];
    const float* ea1 = (const float*)d_in[5];
    const float* ea2 = (const float*)d_in[6];
    const float* W   = (const float*)d_in[7];
    const int*  eidx = (const int*)d_in[8];
    float* out = (float*)d_out;

    hist_mix_kernel<<<HIST_BLOCKS + MIX_BLOCKS, FUSED_THREADS>>>(eidx, h0, h1, h2, W);
    scan_kernel<<<1, 1024>>>();
    scatter_pack_kernel<<<(N_EDGES + 255) / 256, 256>>>(eidx, ea0, ea1, ea2);
    node_kernel<<<(N_NODES * 32 + 255) / 256, 256>>>(out);
}